// round 6
// baseline (speedup 1.0000x reference)
#include <cuda_runtime.h>
#include <cuda_fp16.h>
#include <cstdint>

#define NN 4096
#define DD 64
#define NITER 50
#define REGI 10.0f
#define INV_REG 0.1f
#define EPSF 1e-16f
#define AB (1.0f / 4096.0f)
#define INV_SCALE (1.0f / 262144.0f)   // 2^-18
#define LN_SCALE 12.476649250079f      // 18*ln2
#define NBLK 256
#define NTHR 512
#define DSM_BYTES 52224

// ---------------- persistent device state (no cudaMalloc allowed) ----------
__device__ uint4 g_E4[(size_t)NN * NN / 8];   // E*2^18 fp16, 32 MiB (L2-resident)
__device__ float g_xT[DD * NN];
__device__ float g_yT[DD * NN];
__device__ __align__(16) float g_xs[NN], g_ys[NN];
__device__ __align__(16) float g_su[NN], g_sv[NN];
__device__ float g_part[NBLK];
__device__ unsigned g_barCount;
__device__ unsigned g_barGen;

extern __shared__ float dsm[];

// ---------------- packed fp32x2 helpers ------------------------------------
__device__ __forceinline__ unsigned long long pk2(float lo, float hi) {
    unsigned long long r;
    asm("mov.b64 %0, {%1, %2};" : "=l"(r) : "f"(lo), "f"(hi));
    return r;
}
__device__ __forceinline__ void ffma2(unsigned long long& d, unsigned long long a,
                                      unsigned long long b) {
    asm("fma.rn.f32x2 %0, %1, %2, %0;" : "+l"(d) : "l"(a), "l"(b));
}
__device__ __forceinline__ float2 upk(unsigned long long v) {
    float2 r;
    asm("mov.b64 {%0, %1}, %2;" : "=f"(r.x), "=f"(r.y) : "l"(v));
    return r;
}

// ---------------- fence-free acq/rel grid barrier --------------------------
__device__ __forceinline__ void gsync(unsigned& gen) {
    __syncthreads();
    if (threadIdx.x == 0) {
        unsigned old;
        asm volatile("atom.add.acq_rel.gpu.global.u32 %0, [%1], 1;"
                     : "=r"(old) : "l"(&g_barCount) : "memory");
        if (old == NBLK - 1u) {
            asm volatile("st.relaxed.gpu.global.u32 [%0], 0;"
                         :: "l"(&g_barCount) : "memory");
            asm volatile("red.release.gpu.global.add.u32 [%0], 1;"
                         :: "l"(&g_barGen) : "memory");
        } else {
            unsigned cur;
            do {
                asm volatile("ld.acquire.gpu.global.u32 %0, [%1];"
                             : "=r"(cur) : "l"(&g_barGen) : "memory");
            } while (cur == gen);
        }
    }
    gen++;
    __syncthreads();
}

// ---------------- init: norms, transposes, su, barrier reset ---------------
// grid 256 x 256 threads; block handles 16 rows of x and y.
__global__ __launch_bounds__(256) void k_init(const float* __restrict__ x,
                                              const float* __restrict__ y) {
    __shared__ float s[16 * 65];
    const int tid = threadIdx.x;
    const int b = blockIdx.x;
    const int w = tid >> 5, l = tid & 31;

    if (b == 0 && tid == 0) { g_barCount = 0; g_barGen = 0; }
    // norms: warp per row, 2 rounds
#pragma unroll
    for (int rr = 0; rr < 2; rr++) {
        const int row = b * 16 + rr * 8 + w;
        float2 vx = *(const float2*)(x + (size_t)row * DD + 2 * l);
        float sx = vx.x * vx.x + vx.y * vx.y;
        float2 vy = *(const float2*)(y + (size_t)row * DD + 2 * l);
        float sy = vy.x * vy.x + vy.y * vy.y;
#pragma unroll
        for (int o = 16; o; o >>= 1) {
            sx += __shfl_xor_sync(~0u, sx, o);
            sy += __shfl_xor_sync(~0u, sy, o);
        }
        if (l == 0) { g_xs[row] = sx; g_ys[row] = sy; }
    }
    if (tid < 16) g_su[b * 16 + tid] = AB;
    // transpose x slab
    for (int i = tid; i < 16 * 64; i += 256) {
        int r = i >> 6, k = i & 63;
        s[r * 65 + k] = x[(size_t)(b * 16 + r) * DD + k];
    }
    __syncthreads();
    for (int i = tid; i < 16 * 64; i += 256) {
        int k = i >> 4, c = i & 15;
        g_xT[(size_t)k * NN + b * 16 + c] = s[c * 65 + k];
    }
    __syncthreads();
    // transpose y slab
    for (int i = tid; i < 16 * 64; i += 256) {
        int r = i >> 6, k = i & 63;
        s[r * 65 + k] = y[(size_t)(b * 16 + r) * DD + k];
    }
    __syncthreads();
    for (int i = tid; i < 16 * 64; i += 256) {
        int k = i >> 4, c = i & 15;
        g_yT[(size_t)k * NN + b * 16 + c] = s[c * 65 + k];
    }
}

// ---------------- persistent: build E + 50 iterations + loss ---------------
__global__ __launch_bounds__(NTHR, 2) void k_persist(float* __restrict__ out) {
    const int tid = threadIdx.x;
    const int b = blockIdx.x;
    const int w = tid >> 5, l = tid & 31;
    unsigned gen = 0;

    // ============ phase 1: build E, 2048 tiles of 128x64, 8 per block ======
    {
        float* Xs = dsm;                 // [64][132]
        float* Ys = dsm + 64 * 132;      // [64][68]
        const int ty = tid >> 4;         // 32 row-groups of 4
        const int tx = tid & 15;         // 16 col-quads of 4
        for (int t = 0; t < 8; t++) {
            const int id = b + t * NBLK;
            const int i0 = (id >> 6) * 128, j0 = (id & 63) * 64;
#pragma unroll
            for (int r = 0; r < 4; r++) {
                int idx = tid + r * NTHR;          // 2048 float4 of Xs
                int k = idx >> 5, c4 = idx & 31;
                *(float4*)&Xs[k * 132 + c4 * 4] =
                    __ldcg((const float4*)(g_xT + (size_t)k * NN + i0 + c4 * 4));
            }
#pragma unroll
            for (int r = 0; r < 2; r++) {
                int idx = tid + r * NTHR;          // 1024 float4 of Ys
                int k = idx >> 4, c4 = idx & 15;
                *(float4*)&Ys[k * 68 + c4 * 4] =
                    __ldcg((const float4*)(g_yT + (size_t)k * NN + j0 + c4 * 4));
            }
            __syncthreads();
            unsigned long long acc2[4][2] = {};
#pragma unroll 8
            for (int k = 0; k < 64; k++) {
                float4 a4 = *(const float4*)&Xs[k * 132 + ty * 4];
                const float2* yp = (const float2*)&Ys[k * 68 + tx * 4];
                float2 bl = yp[0], bh = yp[1];
                unsigned long long b0 = pk2(bl.x, bl.y);
                unsigned long long b1 = pk2(bh.x, bh.y);
                unsigned long long aa;
                aa = pk2(a4.x, a4.x); ffma2(acc2[0][0], aa, b0); ffma2(acc2[0][1], aa, b1);
                aa = pk2(a4.y, a4.y); ffma2(acc2[1][0], aa, b0); ffma2(acc2[1][1], aa, b1);
                aa = pk2(a4.z, a4.z); ffma2(acc2[2][0], aa, b0); ffma2(acc2[2][1], aa, b1);
                aa = pk2(a4.w, a4.w); ffma2(acc2[3][0], aa, b0); ffma2(acc2[3][1], aa, b1);
            }
            float xr[4], yc[4];
#pragma unroll
            for (int r = 0; r < 4; r++) xr[r] = __ldcg(&g_xs[i0 + ty * 4 + r]);
            {
                float4 y4 = __ldcg((const float4*)&g_ys[j0 + tx * 4]);
                yc[0] = y4.x; yc[1] = y4.y; yc[2] = y4.z; yc[3] = y4.w;
            }
            __half* Eh = (__half*)g_E4;
#pragma unroll
            for (int r = 0; r < 4; r++) {
                float2 d01 = upk(acc2[r][0]);
                float2 d23 = upk(acc2[r][1]);
                float e0 = __expf((2.f * d01.x - xr[r] - yc[0]) * INV_REG + LN_SCALE);
                float e1 = __expf((2.f * d01.y - xr[r] - yc[1]) * INV_REG + LN_SCALE);
                float e2 = __expf((2.f * d23.x - xr[r] - yc[2]) * INV_REG + LN_SCALE);
                float e3 = __expf((2.f * d23.y - xr[r] - yc[3]) * INV_REG + LN_SCALE);
                union { uint2 u; __half2 h[2]; } pk;
                pk.h[0] = __floats2half2_rn(e0, e1);
                pk.h[1] = __floats2half2_rn(e2, e3);
                *(uint2*)(Eh + (size_t)(i0 + ty * 4 + r) * NN + j0 + tx * 4) = pk.u;
            }
            __syncthreads();
        }
    }
    gsync(gen);

    const uint2* E2 = (const uint2*)g_E4;

    // ============ phase 2: 50 Sinkhorn iterations ==========================
    for (int it = 0; it < NITER; it++) {
        // ---- col pass: block owns cols [16b, 16b+16)
        {
            float* ssu = dsm;                      // [4096]
            float* cred = dsm + 4096;              // [16][16]
#pragma unroll
            for (int r = 0; r < 2; r++) {
                int idx = tid + r * NTHR;
                float4 v = __ldcg((const float4*)g_su + idx);
                *(float4*)&ssu[idx * 4] = v;
            }
            __syncthreads();
            const int qi = l & 3, ro = l >> 2;     // 4 col-quads x 8 row-offsets
            const uint2* ep = E2 + (size_t)(w * 256 + ro) * (NN / 4) + b * 4 + qi;
            const float* sup = ssu + w * 256 + ro;
            float a0 = 0.f, a1 = 0.f, a2 = 0.f, a3 = 0.f;
#pragma unroll 8
            for (int st = 0; st < 32; st++) {
                uint2 ev = ep[(size_t)(st * 8) * (NN / 4)];
                float s = sup[st * 8];
                float2 e01 = __half22float2(*(const __half2*)&ev.x);
                float2 e23 = __half22float2(*(const __half2*)&ev.y);
                a0 += e01.x * s; a1 += e01.y * s; a2 += e23.x * s; a3 += e23.y * s;
            }
#pragma unroll
            for (int o = 4; o <= 16; o <<= 1) {
                a0 += __shfl_xor_sync(~0u, a0, o);
                a1 += __shfl_xor_sync(~0u, a1, o);
                a2 += __shfl_xor_sync(~0u, a2, o);
                a3 += __shfl_xor_sync(~0u, a3, o);
            }
            if (l < 4) *(float4*)&cred[w * 16 + l * 4] = make_float4(a0, a1, a2, a3);
            __syncthreads();
            if (tid < 16) {
                float s = 0.f;
#pragma unroll
                for (int q = 0; q < 16; q++) s += cred[q * 16 + tid];
                g_sv[b * 16 + tid] = AB / (s * INV_SCALE + EPSF);
            }
        }
        gsync(gen);
        // ---- row pass: block owns rows [16b, 16b+16), warp per row
        {
            float* ssv = dsm;                      // [4096]
#pragma unroll
            for (int r = 0; r < 2; r++) {
                int idx = tid + r * NTHR;
                float4 v = __ldcg((const float4*)g_sv + idx);
                *(float4*)&ssv[idx * 4] = v;
            }
            __syncthreads();
            const int row = b * 16 + w;
            const uint4* ep = g_E4 + (size_t)row * (NN / 8) + l;
            float acc = 0.f;
#pragma unroll 4
            for (int itq = 0; itq < 16; itq++) {
                uint4 ev = ep[itq * 32];
                const float4* vp = (const float4*)&ssv[(itq * 32 + l) * 8];
                float4 v0 = vp[0], v1 = vp[1];
                const __half2* eh = (const __half2*)&ev;
                float2 e0 = __half22float2(eh[0]);
                float2 e1 = __half22float2(eh[1]);
                float2 e2 = __half22float2(eh[2]);
                float2 e3 = __half22float2(eh[3]);
                acc += e0.x * v0.x + e0.y * v0.y + e1.x * v0.z + e1.y * v0.w
                     + e2.x * v1.x + e2.y * v1.y + e3.x * v1.z + e3.y * v1.w;
            }
#pragma unroll
            for (int o = 16; o; o >>= 1) acc += __shfl_xor_sync(~0u, acc, o);
            if (l == 0) g_su[row] = AB / (acc * INV_SCALE + EPSF);
        }
        gsync(gen);
    }

    // ============ phase 2b: loss sweep over this block's 16 rows ===========
    {
        float* ssv = dsm;
        float* wred = dsm + 4096;
#pragma unroll
        for (int r = 0; r < 2; r++) {
            int idx = tid + r * NTHR;
            float4 v = __ldcg((const float4*)g_sv + idx);
            *(float4*)&ssv[idx * 4] = v;
        }
        __syncthreads();
        const int row = b * 16 + w;
        const uint4* ep = g_E4 + (size_t)row * (NN / 8) + l;
        float acc = 0.f;
#pragma unroll 1
        for (int itq = 0; itq < 16; itq++) {
            uint4 ev = ep[itq * 32];
            const float4* vp = (const float4*)&ssv[(itq * 32 + l) * 8];
            float4 v0 = vp[0], v1 = vp[1];
            const __half2* eh = (const __half2*)&ev;
            float2 ef[4];
            ef[0] = __half22float2(eh[0]);
            ef[1] = __half22float2(eh[1]);
            ef[2] = __half22float2(eh[2]);
            ef[3] = __half22float2(eh[3]);
            float vv[8] = {v0.x, v0.y, v0.z, v0.w, v1.x, v1.y, v1.z, v1.w};
#pragma unroll
            for (int q = 0; q < 4; q++) {
                float ex = ((float*)ef)[2 * q], ey = ((float*)ef)[2 * q + 1];
                float t0 = (ex > 0.f) ? ex * (LN_SCALE - __logf(ex)) : 0.f;
                float t1 = (ey > 0.f) ? ey * (LN_SCALE - __logf(ey)) : 0.f;
                acc += t0 * vv[2 * q] + t1 * vv[2 * q + 1];
            }
        }
#pragma unroll
        for (int o = 16; o; o >>= 1) acc += __shfl_xor_sync(~0u, acc, o);
        if (l == 0) wred[w] = acc * __ldcg(&g_su[row]);
        __syncthreads();
        if (tid == 0) {
            float s = 0.f;
#pragma unroll
            for (int q = 0; q < 16; q++) s += wred[q];
            g_part[b] = REGI * INV_SCALE * s;
        }
    }
    gsync(gen);

    // ============ phase 3: final reduction (block 0) =======================
    if (b == 0 && tid < 256) {
        float v = __ldcg(&g_part[tid]);
#pragma unroll
        for (int o = 16; o; o >>= 1) v += __shfl_xor_sync(~0u, v, o);
        float* fs = dsm;
        if (l == 0) fs[w] = v;
        __syncthreads();
        if (tid == 0) {
            float s = 0.f;
#pragma unroll
            for (int q = 0; q < 8; q++) s += fs[q];
            out[0] = s;
        }
    }
}

// ---------------------------------------------------------------------------
extern "C" void kernel_launch(void* const* d_in, const int* in_sizes, int n_in,
                              void* d_out, int out_size) {
    const float* x = (const float*)d_in[0];
    const float* y = (const float*)d_in[1];
    float* out = (float*)d_out;

    cudaFuncSetAttribute(k_persist, cudaFuncAttributeMaxDynamicSharedMemorySize,
                         DSM_BYTES);
    k_init<<<256, 256>>>(x, y);
    k_persist<<<NBLK, NTHR, DSM_BYTES>>>(out);
}